// round 8
// baseline (speedup 1.0000x reference)
#include <cuda_runtime.h>

// x [B=4096, T=512, D=4], H=32, 2 stacked LSTM layers, gate rows i,f,g,o (0..127),
// head: out[b] = h2[T-1] . W_out + b_out.
// ONE block = TWO batches (A,B); weights in registers; FFMA2 dots; MUFU.TANH;
// partitioned c/h updates (1 task/thread). This round: register diet to 128
// (no x double-buffer, 8 accumulator pairs, indexed smem) -> 4 blocks/SM.
#define TT 512
#define DD 4

typedef unsigned long long ull;

__device__ __forceinline__ ull ffma2(ull a, ull b, ull c) {
    ull d;
    asm("fma.rn.f32x2 %0, %1, %2, %3;" : "=l"(d) : "l"(a), "l"(b), "l"(c));
    return d;
}
__device__ __forceinline__ ull fadd2(ull a, ull b) {
    ull d;
    asm("add.rn.f32x2 %0, %1, %2;" : "=l"(d) : "l"(a), "l"(b));
    return d;
}
__device__ __forceinline__ ull fpack(float lo, float hi) {
    ull d;
    asm("mov.b64 %0, {%1, %2};" : "=l"(d) : "f"(lo), "f"(hi));
    return d;
}
__device__ __forceinline__ float funpack_sum(ull p) {
    float lo, hi;
    asm("mov.b64 {%0, %1}, %2;" : "=f"(lo), "=f"(hi) : "l"(p));
    return lo + hi;
}

__device__ __forceinline__ float tanh_hw(float x) {
    float y;
    asm("tanh.approx.f32 %0, %1;" : "=f"(y) : "f"(x));
    return y;
}
__device__ __forceinline__ float fsig(float x) {
    return fmaf(0.5f, tanh_hw(0.5f * x), 0.5f);
}
__device__ __forceinline__ float ftanh(float x) { return tanh_hw(x); }

__global__ __launch_bounds__(128, 4)
void lstm2_kernel(const float* __restrict__ x,
                  const float* __restrict__ Wih0, const float* __restrict__ Whh0,
                  const float* __restrict__ bih0, const float* __restrict__ bhh0,
                  const float* __restrict__ Wih1, const float* __restrict__ Whh1,
                  const float* __restrict__ bih1, const float* __restrict__ bhh1,
                  const float* __restrict__ Wout, const float* __restrict__ bout,
                  float* __restrict__ out)
{
    const int bA   = blockIdx.x * 2;
    const int tid  = threadIdx.x;          // gate-row index for the dots
    const int gate = tid >> 5;             // warp = gate row-group AND update-task id
    const int lane = tid & 31;

    // H[0]=h1A  H[1]=h1B  H[2]=h0A  H[3]=h0B   (task g updates H[g] from G[g])
    // G[0]=gates(L1,A)  G[1]=(L1,B)  G[2]=(L0,A)  G[3]=(L0,B)
    __shared__ __align__(16) float H[4][32];
    __shared__ float G[4][128];

    // ---- weights resident as f32x2 register pairs, shared by both streams ----
    ull wih0p[2], whh0p[16], wih1p[16], whh1p[16];
    {
        const ulonglong2* r;
        r = reinterpret_cast<const ulonglong2*>(Wih0 + tid * 4);
        { ulonglong2 v = r[0]; wih0p[0] = v.x; wih0p[1] = v.y; }
        r = reinterpret_cast<const ulonglong2*>(Whh0 + tid * 32);
        #pragma unroll
        for (int k = 0; k < 8; ++k) { ulonglong2 v = r[k]; whh0p[2*k] = v.x; whh0p[2*k+1] = v.y; }
        r = reinterpret_cast<const ulonglong2*>(Wih1 + tid * 32);
        #pragma unroll
        for (int k = 0; k < 8; ++k) { ulonglong2 v = r[k]; wih1p[2*k] = v.x; wih1p[2*k+1] = v.y; }
        r = reinterpret_cast<const ulonglong2*>(Whh1 + tid * 32);
        #pragma unroll
        for (int k = 0; k < 8; ++k) { ulonglong2 v = r[k]; whh1p[2*k] = v.x; whh1p[2*k+1] = v.y; }
    }
    const ull bias0p = fpack(bih0[tid] + bhh0[tid], 0.0f);
    const ull bias1p = fpack(bih1[tid] + bhh1[tid], 0.0f);
    const ull ZP = 0ull;

    float cst = 0.0f;                      // this thread's task cell state

    if (tid < 32) { H[0][tid] = 0.0f; H[1][tid] = 0.0f; H[2][tid] = 0.0f; H[3][tid] = 0.0f; }
    __syncthreads();

    const ulonglong2* XA = reinterpret_cast<const ulonglong2*>(x + (size_t)bA * (TT * DD));
    const ulonglong2* XB = XA + TT;        // next batch: TT*DD floats = TT ulonglong2
    const ulonglong2* H1Ap = reinterpret_cast<const ulonglong2*>(H[0]);
    const ulonglong2* H1Bp = reinterpret_cast<const ulonglong2*>(H[1]);
    const ulonglong2* H0Ap = reinterpret_cast<const ulonglong2*>(H[2]);
    const ulonglong2* H0Bp = reinterpret_cast<const ulonglong2*>(H[3]);

    // ================= prologue: layer-0 gates for step 0 (h0 == 0) =================
    {
        ulonglong2 xa = XA[0], xb = XB[0];
        float pA = funpack_sum(fadd2(ffma2(xa.x, wih0p[0], bias0p),
                                     ffma2(xa.y, wih0p[1], ZP)));
        float pB = funpack_sum(fadd2(ffma2(xb.x, wih0p[0], bias0p),
                                     ffma2(xb.y, wih0p[1], ZP)));
        G[2][tid] = (gate == 2) ? ftanh(pA) : fsig(pA);
        G[3][tid] = (gate == 2) ? ftanh(pB) : fsig(pB);
    }
    __syncthreads();
    if (gate >= 2) {   // L0 tasks only at step 0
        const float* gs = G[gate];
        float gi = gs[lane], gf = gs[32 + lane], gg = gs[64 + lane], go = gs[96 + lane];
        cst = fmaf(gf, cst, gi * gg);
        H[gate][lane] = go * tanh_hw(cst);
    }
    __syncthreads();

    // ===== main loop: dots -> BAR -> one update/thread -> BAR =====
    for (int t = 0; t < TT - 1; ++t) {
        // x(t+1) loaded up front; its FMAs applied AFTER the h-dots (latency cover)
        ulonglong2 xvA = XA[t + 1], xvB = XB[t + 1];

        ull sA0 = bias0p, sA1 = ZP;            // L0(t+1) accumulators
        ull sB0 = bias0p, sB1 = ZP;
        ull uA0 = bias1p, uA1 = ZP;            // L1(t) accumulators
        ull uB0 = bias1p, uB1 = ZP;
        #pragma unroll
        for (int k = 0; k < 8; ++k) {
            ulonglong2 aA = H0Ap[k];           // h0A(t): feeds L1 and next-L0
            ulonglong2 hA = H1Ap[k];           // h1A(t-1)
            ulonglong2 aB = H0Bp[k];
            ulonglong2 hB = H1Bp[k];
            uA0 = ffma2(aA.x, wih1p[2*k],   uA0);
            uA1 = ffma2(aA.y, wih1p[2*k+1], uA1);
            uB0 = ffma2(aB.x, wih1p[2*k],   uB0);
            uB1 = ffma2(aB.y, wih1p[2*k+1], uB1);
            uA0 = ffma2(hA.x, whh1p[2*k],   uA0);
            uA1 = ffma2(hA.y, whh1p[2*k+1], uA1);
            uB0 = ffma2(hB.x, whh1p[2*k],   uB0);
            uB1 = ffma2(hB.y, whh1p[2*k+1], uB1);
            sA0 = ffma2(aA.x, whh0p[2*k],   sA0);
            sA1 = ffma2(aA.y, whh0p[2*k+1], sA1);
            sB0 = ffma2(aB.x, whh0p[2*k],   sB0);
            sB1 = ffma2(aB.y, whh0p[2*k+1], sB1);
        }
        sA0 = ffma2(xvA.x, wih0p[0], sA0);
        sA1 = ffma2(xvA.y, wih0p[1], sA1);
        sB0 = ffma2(xvB.x, wih0p[0], sB0);
        sB1 = ffma2(xvB.y, wih0p[1], sB1);

        float preA1 = funpack_sum(fadd2(uA0, uA1));
        float preB1 = funpack_sum(fadd2(uB0, uB1));
        float preA0 = funpack_sum(fadd2(sA0, sA1));
        float preB0 = funpack_sum(fadd2(sB0, sB1));

        if (gate == 2) {
            G[0][tid] = ftanh(preA1);
            G[1][tid] = ftanh(preB1);
            G[2][tid] = ftanh(preA0);
            G[3][tid] = ftanh(preB0);
        } else {
            G[0][tid] = fsig(preA1);
            G[1][tid] = fsig(preB1);
            G[2][tid] = fsig(preA0);
            G[3][tid] = fsig(preB0);
        }
        __syncthreads();                      // BAR1: gates visible

        {   // ONE update task per thread: warp g -> (G[g] -> H[g])
            const float* gs = G[gate];
            float gi = gs[lane], gf = gs[32 + lane], gg = gs[64 + lane], go = gs[96 + lane];
            cst = fmaf(gf, cst, gi * gg);
            H[gate][lane] = go * tanh_hw(cst);
        }
        __syncthreads();                      // BAR2: h visible for next dots
    }

    // ================= epilogue: L1(TT-1), both batches =================
    {
        ull uA0 = bias1p, uA1 = ZP;
        ull uB0 = bias1p, uB1 = ZP;
        #pragma unroll
        for (int k = 0; k < 8; ++k) {
            ulonglong2 aA = H0Ap[k];
            ulonglong2 hA = H1Ap[k];
            ulonglong2 aB = H0Bp[k];
            ulonglong2 hB = H1Bp[k];
            uA0 = ffma2(aA.x, wih1p[2*k],   uA0);
            uA1 = ffma2(aA.y, wih1p[2*k+1], uA1);
            uB0 = ffma2(aB.x, wih1p[2*k],   uB0);
            uB1 = ffma2(aB.y, wih1p[2*k+1], uB1);
            uA0 = ffma2(hA.x, whh1p[2*k],   uA0);
            uA1 = ffma2(hA.y, whh1p[2*k+1], uA1);
            uB0 = ffma2(hB.x, whh1p[2*k],   uB0);
            uB1 = ffma2(hB.y, whh1p[2*k+1], uB1);
        }
        float preA1 = funpack_sum(fadd2(uA0, uA1));
        float preB1 = funpack_sum(fadd2(uB0, uB1));
        G[0][tid] = (gate == 2) ? ftanh(preA1) : fsig(preA1);
        G[1][tid] = (gate == 2) ? ftanh(preB1) : fsig(preB1);
    }
    __syncthreads();
    if (gate < 2) {   // final L1 updates
        const float* gs = G[gate];
        float gi = gs[lane], gf = gs[32 + lane], gg = gs[64 + lane], go = gs[96 + lane];
        cst = fmaf(gf, cst, gi * gg);
        H[gate][lane] = go * tanh_hw(cst);
    }
    __syncthreads();

    // -------- head: out = h1(final) . Wout + bout (warp 0, both batches) --------
    if (tid < 32) {
        float w = Wout[lane];
        float vA = H[0][lane] * w;
        float vB = H[1][lane] * w;
        #pragma unroll
        for (int o = 16; o > 0; o >>= 1) {
            vA += __shfl_down_sync(0xffffffffu, vA, o);
            vB += __shfl_down_sync(0xffffffffu, vB, o);
        }
        if (lane == 0) {
            float bo = bout[0];
            out[bA]     = vA + bo;
            out[bA + 1] = vB + bo;
        }
    }
}

extern "C" void kernel_launch(void* const* d_in, const int* in_sizes, int n_in,
                              void* d_out, int out_size)
{
    const float* x    = (const float*)d_in[0];
    const float* Wih0 = (const float*)d_in[1];
    const float* Whh0 = (const float*)d_in[2];
    const float* bih0 = (const float*)d_in[3];
    const float* bhh0 = (const float*)d_in[4];
    const float* Wih1 = (const float*)d_in[5];
    const float* Whh1 = (const float*)d_in[6];
    const float* bih1 = (const float*)d_in[7];
    const float* bhh1 = (const float*)d_in[8];
    const float* Wout = (const float*)d_in[9];
    const float* bout = (const float*)d_in[10];

    const int B = out_size;     // 4096
    lstm2_kernel<<<B / 2, 128>>>(x, Wih0, Whh0, bih0, bhh0,
                                 Wih1, Whh1, bih1, bhh1,
                                 Wout, bout, (float*)d_out);
}

// round 11
// speedup vs baseline: 1.0355x; 1.0355x over previous
#include <cuda_runtime.h>

// x [B=4096, T=512, D=4], H=32, 2 stacked LSTM layers, gate rows i,f,g,o (0..127),
// head: out[b] = h2[T-1] . W_out + b_out.
// ONE block = TWO batches (A,B); weights in registers; FFMA2 dots; MUFU.TANH;
// partitioned c/h updates; 128 regs -> 4 blocks/SM.
// This round: x loads ROTATED to just-after-consumption (full-step prefetch
// cover with no extra registers) -- fixes R8's DRAM-miss stall on the x stream.
#define TT 512
#define DD 4

typedef unsigned long long ull;

__device__ __forceinline__ ull ffma2(ull a, ull b, ull c) {
    ull d;
    asm("fma.rn.f32x2 %0, %1, %2, %3;" : "=l"(d) : "l"(a), "l"(b), "l"(c));
    return d;
}
__device__ __forceinline__ ull fadd2(ull a, ull b) {
    ull d;
    asm("add.rn.f32x2 %0, %1, %2;" : "=l"(d) : "l"(a), "l"(b));
    return d;
}
__device__ __forceinline__ ull fpack(float lo, float hi) {
    ull d;
    asm("mov.b64 %0, {%1, %2};" : "=l"(d) : "f"(lo), "f"(hi));
    return d;
}
__device__ __forceinline__ float funpack_sum(ull p) {
    float lo, hi;
    asm("mov.b64 {%0, %1}, %2;" : "=f"(lo), "=f"(hi) : "l"(p));
    return lo + hi;
}

__device__ __forceinline__ float tanh_hw(float x) {
    float y;
    asm("tanh.approx.f32 %0, %1;" : "=f"(y) : "f"(x));
    return y;
}
__device__ __forceinline__ float fsig(float x) {
    return fmaf(0.5f, tanh_hw(0.5f * x), 0.5f);
}
__device__ __forceinline__ float ftanh(float x) { return tanh_hw(x); }

__global__ __launch_bounds__(128, 4)
void lstm2_kernel(const float* __restrict__ x,
                  const float* __restrict__ Wih0, const float* __restrict__ Whh0,
                  const float* __restrict__ bih0, const float* __restrict__ bhh0,
                  const float* __restrict__ Wih1, const float* __restrict__ Whh1,
                  const float* __restrict__ bih1, const float* __restrict__ bhh1,
                  const float* __restrict__ Wout, const float* __restrict__ bout,
                  float* __restrict__ out)
{
    const int bA   = blockIdx.x * 2;
    const int tid  = threadIdx.x;          // gate-row index for the dots
    const int gate = tid >> 5;             // warp = gate row-group AND update-task id
    const int lane = tid & 31;

    // H[0]=h1A  H[1]=h1B  H[2]=h0A  H[3]=h0B   (task g updates H[g] from G[g])
    __shared__ __align__(16) float H[4][32];
    __shared__ float G[4][128];

    // ---- weights resident as f32x2 register pairs, shared by both streams ----
    ull wih0p[2], whh0p[16], wih1p[16], whh1p[16];
    {
        const ulonglong2* r;
        r = reinterpret_cast<const ulonglong2*>(Wih0 + tid * 4);
        { ulonglong2 v = r[0]; wih0p[0] = v.x; wih0p[1] = v.y; }
        r = reinterpret_cast<const ulonglong2*>(Whh0 + tid * 32);
        #pragma unroll
        for (int k = 0; k < 8; ++k) { ulonglong2 v = r[k]; whh0p[2*k] = v.x; whh0p[2*k+1] = v.y; }
        r = reinterpret_cast<const ulonglong2*>(Wih1 + tid * 32);
        #pragma unroll
        for (int k = 0; k < 8; ++k) { ulonglong2 v = r[k]; wih1p[2*k] = v.x; wih1p[2*k+1] = v.y; }
        r = reinterpret_cast<const ulonglong2*>(Whh1 + tid * 32);
        #pragma unroll
        for (int k = 0; k < 8; ++k) { ulonglong2 v = r[k]; whh1p[2*k] = v.x; whh1p[2*k+1] = v.y; }
    }
    const ull bias0p = fpack(bih0[tid] + bhh0[tid], 0.0f);
    const ull bias1p = fpack(bih1[tid] + bhh1[tid], 0.0f);
    const ull ZP = 0ull;

    float cst = 0.0f;                      // this thread's task cell state

    if (tid < 32) { H[0][tid] = 0.0f; H[1][tid] = 0.0f; H[2][tid] = 0.0f; H[3][tid] = 0.0f; }
    __syncthreads();

    const ulonglong2* XA = reinterpret_cast<const ulonglong2*>(x + (size_t)bA * (TT * DD));
    const ulonglong2* XB = XA + TT;
    const ulonglong2* H1Ap = reinterpret_cast<const ulonglong2*>(H[0]);
    const ulonglong2* H1Bp = reinterpret_cast<const ulonglong2*>(H[1]);
    const ulonglong2* H0Ap = reinterpret_cast<const ulonglong2*>(H[2]);
    const ulonglong2* H0Bp = reinterpret_cast<const ulonglong2*>(H[3]);

    // ================= prologue: layer-0 gates for step 0 (h0 == 0) =================
    {
        ulonglong2 xa = XA[0], xb = XB[0];
        float pA = funpack_sum(fadd2(ffma2(xa.x, wih0p[0], bias0p),
                                     ffma2(xa.y, wih0p[1], ZP)));
        float pB = funpack_sum(fadd2(ffma2(xb.x, wih0p[0], bias0p),
                                     ffma2(xb.y, wih0p[1], ZP)));
        G[2][tid] = (gate == 2) ? ftanh(pA) : fsig(pA);
        G[3][tid] = (gate == 2) ? ftanh(pB) : fsig(pB);
    }
    // prefetch x(1): consumed in iteration t=0's k-loop tail (cover = prologue update)
    ulonglong2 xvA = XA[1], xvB = XB[1];
    __syncthreads();
    if (gate >= 2) {   // L0 tasks only at step 0
        const float* gs = G[gate];
        float gi = gs[lane], gf = gs[32 + lane], gg = gs[64 + lane], go = gs[96 + lane];
        cst = fmaf(gf, cst, gi * gg);
        H[gate][lane] = go * tanh_hw(cst);
    }
    __syncthreads();

    // ===== main loop: dots -> rotate x load -> BAR -> one update/thread -> BAR =====
    for (int t = 0; t < TT - 1; ++t) {
        ull sA0 = bias0p, sA1 = ZP;            // L0(t+1) accumulators
        ull sB0 = bias0p, sB1 = ZP;
        ull uA0 = bias1p, uA1 = ZP;            // L1(t) accumulators
        ull uB0 = bias1p, uB1 = ZP;
        #pragma unroll
        for (int k = 0; k < 8; ++k) {
            ulonglong2 aA = H0Ap[k];           // h0A(t): feeds L1 and next-L0
            ulonglong2 hA = H1Ap[k];           // h1A(t-1)
            ulonglong2 aB = H0Bp[k];
            ulonglong2 hB = H1Bp[k];
            uA0 = ffma2(aA.x, wih1p[2*k],   uA0);
            uA1 = ffma2(aA.y, wih1p[2*k+1], uA1);
            uB0 = ffma2(aB.x, wih1p[2*k],   uB0);
            uB1 = ffma2(aB.y, wih1p[2*k+1], uB1);
            uA0 = ffma2(hA.x, whh1p[2*k],   uA0);
            uA1 = ffma2(hA.y, whh1p[2*k+1], uA1);
            uB0 = ffma2(hB.x, whh1p[2*k],   uB0);
            uB1 = ffma2(hB.y, whh1p[2*k+1], uB1);
            sA0 = ffma2(aA.x, whh0p[2*k],   sA0);
            sA1 = ffma2(aA.y, whh0p[2*k+1], sA1);
            sB0 = ffma2(aB.x, whh0p[2*k],   sB0);
            sB1 = ffma2(aB.y, whh0p[2*k+1], sB1);
        }
        // consume x(t+1)
        sA0 = ffma2(xvA.x, wih0p[0], sA0);
        sA1 = ffma2(xvA.y, wih0p[1], sA1);
        sB0 = ffma2(xvB.x, wih0p[0], sB0);
        sB1 = ffma2(xvB.y, wih0p[1], sB1);

        // ROTATE: immediately reload the same registers with x(t+2)
        // (cover = activations + BAR1 + update + BAR2 + next k-loop ≈ full step)
        {
            const int ti = (t + 2 < TT) ? (t + 2) : (TT - 1);
            xvA = XA[ti];
            xvB = XB[ti];
        }

        float preA1 = funpack_sum(fadd2(uA0, uA1));
        float preB1 = funpack_sum(fadd2(uB0, uB1));
        float preA0 = funpack_sum(fadd2(sA0, sA1));
        float preB0 = funpack_sum(fadd2(sB0, sB1));

        if (gate == 2) {
            G[0][tid] = ftanh(preA1);
            G[1][tid] = ftanh(preB1);
            G[2][tid] = ftanh(preA0);
            G[3][tid] = ftanh(preB0);
        } else {
            G[0][tid] = fsig(preA1);
            G[1][tid] = fsig(preB1);
            G[2][tid] = fsig(preA0);
            G[3][tid] = fsig(preB0);
        }
        __syncthreads();                      // BAR1: gates visible

        {   // ONE update task per thread: warp g -> (G[g] -> H[g])
            const float* gs = G[gate];
            float gi = gs[lane], gf = gs[32 + lane], gg = gs[64 + lane], go = gs[96 + lane];
            cst = fmaf(gf, cst, gi * gg);
            H[gate][lane] = go * tanh_hw(cst);
        }
        __syncthreads();                      // BAR2: h visible for next dots
    }

    // ================= epilogue: L1(TT-1), both batches =================
    {
        ull uA0 = bias1p, uA1 = ZP;
        ull uB0 = bias1p, uB1 = ZP;
        #pragma unroll
        for (int k = 0; k < 8; ++k) {
            ulonglong2 aA = H0Ap[k];
            ulonglong2 hA = H1Ap[k];
            ulonglong2 aB = H0Bp[k];
            ulonglong2 hB = H1Bp[k];
            uA0 = ffma2(aA.x, wih1p[2*k],   uA0);
            uA1 = ffma2(aA.y, wih1p[2*k+1], uA1);
            uB0 = ffma2(aB.x, wih1p[2*k],   uB0);
            uB1 = ffma2(aB.y, wih1p[2*k+1], uB1);
            uA0 = ffma2(hA.x, whh1p[2*k],   uA0);
            uA1 = ffma2(hA.y, whh1p[2*k+1], uA1);
            uB0 = ffma2(hB.x, whh1p[2*k],   uB0);
            uB1 = ffma2(hB.y, whh1p[2*k+1], uB1);
        }
        float preA1 = funpack_sum(fadd2(uA0, uA1));
        float preB1 = funpack_sum(fadd2(uB0, uB1));
        G[0][tid] = (gate == 2) ? ftanh(preA1) : fsig(preA1);
        G[1][tid] = (gate == 2) ? ftanh(preB1) : fsig(preB1);
    }
    __syncthreads();
    if (gate < 2) {   // final L1 updates
        const float* gs = G[gate];
        float gi = gs[lane], gf = gs[32 + lane], gg = gs[64 + lane], go = gs[96 + lane];
        cst = fmaf(gf, cst, gi * gg);
        H[gate][lane] = go * tanh_hw(cst);
    }
    __syncthreads();

    // -------- head: out = h1(final) . Wout + bout (warp 0, both batches) --------
    if (tid < 32) {
        float w = Wout[lane];
        float vA = H[0][lane] * w;
        float vB = H[1][lane] * w;
        #pragma unroll
        for (int o = 16; o > 0; o >>= 1) {
            vA += __shfl_down_sync(0xffffffffu, vA, o);
            vB += __shfl_down_sync(0xffffffffu, vB, o);
        }
        if (lane == 0) {
            float bo = bout[0];
            out[bA]     = vA + bo;
            out[bA + 1] = vB + bo;
        }
    }
}

extern "C" void kernel_launch(void* const* d_in, const int* in_sizes, int n_in,
                              void* d_out, int out_size)
{
    const float* x    = (const float*)d_in[0];
    const float* Wih0 = (const float*)d_in[1];
    const float* Whh0 = (const float*)d_in[2];
    const float* bih0 = (const float*)d_in[3];
    const float* bhh0 = (const float*)d_in[4];
    const float* Wih1 = (const float*)d_in[5];
    const float* Whh1 = (const float*)d_in[6];
    const float* bih1 = (const float*)d_in[7];
    const float* bhh1 = (const float*)d_in[8];
    const float* Wout = (const float*)d_in[9];
    const float* bout = (const float*)d_in[10];

    const int B = out_size;     // 4096
    lstm2_kernel<<<B / 2, 128>>>(x, Wih0, Whh0, bih0, bhh0,
                                 Wih1, Whh1, bih1, bhh1,
                                 Wout, bout, (float*)d_out);
}

// round 12
// speedup vs baseline: 1.2512x; 1.2083x over previous
#include <cuda_runtime.h>

// x [B=4096, T=512, D=4], H=32, 2 stacked LSTM layers, gate rows i,f,g,o (0..127),
// head: out[b] = h2[T-1] . W_out + b_out.
// R7 base config (3 blocks/SM, weights in regs, FFMA2, MUFU.TANH, partitioned
// updates, 2 barriers/step) extended to THREE batches per block (A,B,C) with
// lean per-batch accumulators and rotated x prefetch. Waves 4.61 -> 3.08.
#define TT 512
#define DD 4

typedef unsigned long long ull;

__device__ __forceinline__ ull ffma2(ull a, ull b, ull c) {
    ull d;
    asm("fma.rn.f32x2 %0, %1, %2, %3;" : "=l"(d) : "l"(a), "l"(b), "l"(c));
    return d;
}
__device__ __forceinline__ ull fadd2(ull a, ull b) {
    ull d;
    asm("add.rn.f32x2 %0, %1, %2;" : "=l"(d) : "l"(a), "l"(b));
    return d;
}
__device__ __forceinline__ ull fpack(float lo, float hi) {
    ull d;
    asm("mov.b64 %0, {%1, %2};" : "=l"(d) : "f"(lo), "f"(hi));
    return d;
}
__device__ __forceinline__ float funpack_sum(ull p) {
    float lo, hi;
    asm("mov.b64 {%0, %1}, %2;" : "=f"(lo), "=f"(hi) : "l"(p));
    return lo + hi;
}

__device__ __forceinline__ float tanh_hw(float x) {
    float y;
    asm("tanh.approx.f32 %0, %1;" : "=f"(y) : "f"(x));
    return y;
}
__device__ __forceinline__ float fsig(float x) {
    return fmaf(0.5f, tanh_hw(0.5f * x), 0.5f);
}
__device__ __forceinline__ float ftanh(float x) { return tanh_hw(x); }

#define NBATCH 3

__global__ __launch_bounds__(128, 3)
void lstm2_kernel(const float* __restrict__ x,
                  const float* __restrict__ Wih0, const float* __restrict__ Whh0,
                  const float* __restrict__ bih0, const float* __restrict__ bhh0,
                  const float* __restrict__ Wih1, const float* __restrict__ Whh1,
                  const float* __restrict__ bih1, const float* __restrict__ bhh1,
                  const float* __restrict__ Wout, const float* __restrict__ bout,
                  float* __restrict__ out, int Btot)
{
    const int b0   = blockIdx.x * NBATCH;
    const int tid  = threadIdx.x;          // gate-row index for the dots
    const int gate = tid >> 5;             // warp id: gate row-group & update tasks
    const int lane = tid & 31;

    // H/G index: 0=(L1,A) 1=(L1,B) 2=(L1,C) 3=(L0,A) 4=(L0,B) 5=(L0,C)
    __shared__ __align__(16) float H[6][32];
    __shared__ float G[6][128];

    // ---- weights resident as f32x2 register pairs, shared by all 3 streams ----
    ull wih0p[2], whh0p[16], wih1p[16], whh1p[16];
    {
        const ulonglong2* r;
        r = reinterpret_cast<const ulonglong2*>(Wih0 + tid * 4);
        { ulonglong2 v = r[0]; wih0p[0] = v.x; wih0p[1] = v.y; }
        r = reinterpret_cast<const ulonglong2*>(Whh0 + tid * 32);
        #pragma unroll
        for (int k = 0; k < 8; ++k) { ulonglong2 v = r[k]; whh0p[2*k] = v.x; whh0p[2*k+1] = v.y; }
        r = reinterpret_cast<const ulonglong2*>(Wih1 + tid * 32);
        #pragma unroll
        for (int k = 0; k < 8; ++k) { ulonglong2 v = r[k]; wih1p[2*k] = v.x; wih1p[2*k+1] = v.y; }
        r = reinterpret_cast<const ulonglong2*>(Whh1 + tid * 32);
        #pragma unroll
        for (int k = 0; k < 8; ++k) { ulonglong2 v = r[k]; whh1p[2*k] = v.x; whh1p[2*k+1] = v.y; }
    }
    const ull bias0p = fpack(bih0[tid] + bhh0[tid], 0.0f);
    const ull bias1p = fpack(bih1[tid] + bhh1[tid], 0.0f);
    const ull ZP = 0ull;

    // update tasks: warp w -> task w; warps 0,1 additionally -> tasks 4,5
    const int task2 = (gate < 2) ? (4 + gate) : -1;
    float cst1 = 0.0f, cst2 = 0.0f;

    if (tid < 32) {
        #pragma unroll
        for (int a = 0; a < 6; ++a) H[a][tid] = 0.0f;
    }
    __syncthreads();

    // batch x pointers (clamped for the possibly-partial last block)
    const ulonglong2* Xb = reinterpret_cast<const ulonglong2*>(x);
    const ulonglong2* XA = Xb + (size_t)b0 * TT;
    const ulonglong2* XB = (b0 + 1 < Btot) ? XA + TT     : XA;
    const ulonglong2* XC = (b0 + 2 < Btot) ? XA + 2 * TT : XA;

    const ulonglong2* H1A = reinterpret_cast<const ulonglong2*>(H[0]);
    const ulonglong2* H1B = reinterpret_cast<const ulonglong2*>(H[1]);
    const ulonglong2* H1C = reinterpret_cast<const ulonglong2*>(H[2]);
    const ulonglong2* H0A = reinterpret_cast<const ulonglong2*>(H[3]);
    const ulonglong2* H0B = reinterpret_cast<const ulonglong2*>(H[4]);
    const ulonglong2* H0C = reinterpret_cast<const ulonglong2*>(H[5]);

    // ================= prologue: layer-0 gates for step 0 (h0 == 0) =================
    {
        ulonglong2 xa = XA[0], xb = XB[0], xc = XC[0];
        float pA = funpack_sum(fadd2(ffma2(xa.x, wih0p[0], bias0p),
                                     ffma2(xa.y, wih0p[1], ZP)));
        float pB = funpack_sum(fadd2(ffma2(xb.x, wih0p[0], bias0p),
                                     ffma2(xb.y, wih0p[1], ZP)));
        float pC = funpack_sum(fadd2(ffma2(xc.x, wih0p[0], bias0p),
                                     ffma2(xc.y, wih0p[1], ZP)));
        if (gate == 2) {
            G[3][tid] = ftanh(pA); G[4][tid] = ftanh(pB); G[5][tid] = ftanh(pC);
        } else {
            G[3][tid] = fsig(pA);  G[4][tid] = fsig(pB);  G[5][tid] = fsig(pC);
        }
    }
    ulonglong2 xvA = XA[1], xvB = XB[1], xvC = XC[1];   // x for step 1
    __syncthreads();
    // step-0 L0 updates: task 3 on warp3 (slot1), tasks 4,5 on warps 0,1 (slot2)
    if (gate == 3) {
        const float* gs = G[3];
        float gi = gs[lane], gf = gs[32+lane], gg = gs[64+lane], go = gs[96+lane];
        cst1 = fmaf(gf, cst1, gi * gg);
        H[3][lane] = go * tanh_hw(cst1);
    }
    if (task2 >= 0) {
        const float* gs = G[task2];
        float gi = gs[lane], gf = gs[32+lane], gg = gs[64+lane], go = gs[96+lane];
        cst2 = fmaf(gf, cst2, gi * gg);
        H[task2][lane] = go * tanh_hw(cst2);
    }
    __syncthreads();

    // ===== main loop: dots(3 batches) -> rotate x -> BAR -> updates -> BAR =====
    for (int t = 0; t < TT - 1; ++t) {
        ull sA0 = bias0p, sA1 = ZP, sB0 = bias0p, sB1 = ZP, sC0 = bias0p, sC1 = ZP;
        ull uA0 = bias1p, uA1 = ZP, uB0 = bias1p, uB1 = ZP, uC0 = bias1p, uC1 = ZP;
        #pragma unroll
        for (int k = 0; k < 8; ++k) {
            ulonglong2 aA = H0A[k], hA = H1A[k];
            uA0 = ffma2(aA.x, wih1p[2*k],   uA0);
            uA1 = ffma2(aA.y, wih1p[2*k+1], uA1);
            uA0 = ffma2(hA.x, whh1p[2*k],   uA0);
            uA1 = ffma2(hA.y, whh1p[2*k+1], uA1);
            sA0 = ffma2(aA.x, whh0p[2*k],   sA0);
            sA1 = ffma2(aA.y, whh0p[2*k+1], sA1);
            ulonglong2 aB = H0B[k], hB = H1B[k];
            uB0 = ffma2(aB.x, wih1p[2*k],   uB0);
            uB1 = ffma2(aB.y, wih1p[2*k+1], uB1);
            uB0 = ffma2(hB.x, whh1p[2*k],   uB0);
            uB1 = ffma2(hB.y, whh1p[2*k+1], uB1);
            sB0 = ffma2(aB.x, whh0p[2*k],   sB0);
            sB1 = ffma2(aB.y, whh0p[2*k+1], sB1);
            ulonglong2 aC = H0C[k], hC = H1C[k];
            uC0 = ffma2(aC.x, wih1p[2*k],   uC0);
            uC1 = ffma2(aC.y, wih1p[2*k+1], uC1);
            uC0 = ffma2(hC.x, whh1p[2*k],   uC0);
            uC1 = ffma2(hC.y, whh1p[2*k+1], uC1);
            sC0 = ffma2(aC.x, whh0p[2*k],   sC0);
            sC1 = ffma2(aC.y, whh0p[2*k+1], sC1);
        }
        // consume x(t+1), then immediately rotate-load x(t+2) (full-step cover)
        sA0 = ffma2(xvA.x, wih0p[0], sA0);
        sA1 = ffma2(xvA.y, wih0p[1], sA1);
        sB0 = ffma2(xvB.x, wih0p[0], sB0);
        sB1 = ffma2(xvB.y, wih0p[1], sB1);
        sC0 = ffma2(xvC.x, wih0p[0], sC0);
        sC1 = ffma2(xvC.y, wih0p[1], sC1);
        {
            const int ti = (t + 2 < TT) ? (t + 2) : (TT - 1);
            xvA = XA[ti]; xvB = XB[ti]; xvC = XC[ti];
        }

        float pA1 = funpack_sum(fadd2(uA0, uA1));
        float pB1 = funpack_sum(fadd2(uB0, uB1));
        float pC1 = funpack_sum(fadd2(uC0, uC1));
        float pA0 = funpack_sum(fadd2(sA0, sA1));
        float pB0 = funpack_sum(fadd2(sB0, sB1));
        float pC0 = funpack_sum(fadd2(sC0, sC1));

        if (gate == 2) {
            G[0][tid] = ftanh(pA1); G[1][tid] = ftanh(pB1); G[2][tid] = ftanh(pC1);
            G[3][tid] = ftanh(pA0); G[4][tid] = ftanh(pB0); G[5][tid] = ftanh(pC0);
        } else {
            G[0][tid] = fsig(pA1);  G[1][tid] = fsig(pB1);  G[2][tid] = fsig(pC1);
            G[3][tid] = fsig(pA0);  G[4][tid] = fsig(pB0);  G[5][tid] = fsig(pC0);
        }
        __syncthreads();                      // BAR1: gates visible

        {   // task 1: warp w -> (G[w] -> H[w])
            const float* gs = G[gate];
            float gi = gs[lane], gf = gs[32+lane], gg = gs[64+lane], go = gs[96+lane];
            cst1 = fmaf(gf, cst1, gi * gg);
            H[gate][lane] = go * tanh_hw(cst1);
        }
        if (task2 >= 0) {   // task 2: warps 0,1 -> tasks 4,5
            const float* gs = G[task2];
            float gi = gs[lane], gf = gs[32+lane], gg = gs[64+lane], go = gs[96+lane];
            cst2 = fmaf(gf, cst2, gi * gg);
            H[task2][lane] = go * tanh_hw(cst2);
        }
        __syncthreads();                      // BAR2: h visible for next dots
    }

    // ================= epilogue: L1(TT-1), all batches =================
    {
        ull uA0 = bias1p, uA1 = ZP, uB0 = bias1p, uB1 = ZP, uC0 = bias1p, uC1 = ZP;
        #pragma unroll
        for (int k = 0; k < 8; ++k) {
            ulonglong2 aA = H0A[k], hA = H1A[k];
            uA0 = ffma2(aA.x, wih1p[2*k],   uA0);
            uA1 = ffma2(aA.y, wih1p[2*k+1], uA1);
            uA0 = ffma2(hA.x, whh1p[2*k],   uA0);
            uA1 = ffma2(hA.y, whh1p[2*k+1], uA1);
            ulonglong2 aB = H0B[k], hB = H1B[k];
            uB0 = ffma2(aB.x, wih1p[2*k],   uB0);
            uB1 = ffma2(aB.y, wih1p[2*k+1], uB1);
            uB0 = ffma2(hB.x, whh1p[2*k],   uB0);
            uB1 = ffma2(hB.y, whh1p[2*k+1], uB1);
            ulonglong2 aC = H0C[k], hC = H1C[k];
            uC0 = ffma2(aC.x, wih1p[2*k],   uC0);
            uC1 = ffma2(aC.y, wih1p[2*k+1], uC1);
            uC0 = ffma2(hC.x, whh1p[2*k],   uC0);
            uC1 = ffma2(hC.y, whh1p[2*k+1], uC1);
        }
        float pA1 = funpack_sum(fadd2(uA0, uA1));
        float pB1 = funpack_sum(fadd2(uB0, uB1));
        float pC1 = funpack_sum(fadd2(uC0, uC1));
        if (gate == 2) {
            G[0][tid] = ftanh(pA1); G[1][tid] = ftanh(pB1); G[2][tid] = ftanh(pC1);
        } else {
            G[0][tid] = fsig(pA1);  G[1][tid] = fsig(pB1);  G[2][tid] = fsig(pC1);
        }
    }
    __syncthreads();
    if (gate < 3) {   // final L1 updates: tasks 0,1,2 on warps 0,1,2
        const float* gs = G[gate];
        float gi = gs[lane], gf = gs[32+lane], gg = gs[64+lane], go = gs[96+lane];
        cst1 = fmaf(gf, cst1, gi * gg);
        H[gate][lane] = go * tanh_hw(cst1);
    }
    __syncthreads();

    // -------- head: warps 0..2 each reduce their batch --------
    if (gate < 3) {
        int b = b0 + gate;
        float v = H[gate][lane] * Wout[lane];
        #pragma unroll
        for (int o = 16; o > 0; o >>= 1)
            v += __shfl_down_sync(0xffffffffu, v, o);
        if (lane == 0 && b < Btot) out[b] = v + bout[0];
    }
}

extern "C" void kernel_launch(void* const* d_in, const int* in_sizes, int n_in,
                              void* d_out, int out_size)
{
    const float* x    = (const float*)d_in[0];
    const float* Wih0 = (const float*)d_in[1];
    const float* Whh0 = (const float*)d_in[2];
    const float* bih0 = (const float*)d_in[3];
    const float* bhh0 = (const float*)d_in[4];
    const float* Wih1 = (const float*)d_in[5];
    const float* Whh1 = (const float*)d_in[6];
    const float* bih1 = (const float*)d_in[7];
    const float* bhh1 = (const float*)d_in[8];
    const float* Wout = (const float*)d_in[9];
    const float* bout = (const float*)d_in[10];

    const int B  = out_size;                 // 4096
    const int nb = (B + NBATCH - 1) / NBATCH;  // 1366
    lstm2_kernel<<<nb, 128>>>(x, Wih0, Whh0, bih0, bhh0,
                              Wih1, Whh1, bih1, bhh1,
                              Wout, bout, (float*)d_out, B);
}